// round 1
// baseline (speedup 1.0000x reference)
#include <cuda_runtime.h>
#include <cuda_bf16.h>

#define NNODES 50000
#define NEDGES 850000
#define IN_DIM 256
#define HID 32
#define H1 8
#define OUT_DIM 64
#define HD1 (H1*HID)   // 256

// ---------------- scratch (static device globals; no allocation) ----------------
__device__ __align__(16) float g_feat1[NNODES * HD1];     // 51.2 MB
__device__ __align__(16) float g_h1[NNODES * HD1];        // 51.2 MB
__device__ __align__(16) float g_feat2[NNODES * OUT_DIM]; // 12.8 MB
__device__ __align__(16) float g_el1[NNODES * H1];
__device__ __align__(16) float g_er1[NNODES * H1];
__device__ __align__(16) float g_el2[NNODES];
__device__ __align__(16) float g_er2[NNODES];
__device__ __align__(16) int   g_cnt[NNODES];
__device__ __align__(16) int   g_off[NNODES + 1];
__device__ __align__(16) int   g_cur[NNODES];
__device__ __align__(16) int   g_csr_src[NEDGES];

// ---------------- simple tiled FP32 GEMM: C[M,Nc] = A[M,K] @ B[K,Nc] ----------------
// BM=BN=64, BK=16, 256 threads, 4x4 microtile. Assumes Nc%64==0, K%16==0; guards M.
__global__ void sgemm_kernel(const float* __restrict__ A, const float* __restrict__ B,
                             float* __restrict__ C, int M, int Nc, int K) {
    __shared__ float As[16][64 + 4];  // transposed: As[k][m]
    __shared__ float Bs[16][64];

    int tid = threadIdx.x;
    int tr = tid >> 4;          // 0..15
    int tc = tid & 15;          // 0..15
    int rowC = blockIdx.y * 64 + tr * 4;
    int colC = blockIdx.x * 64 + tc * 4;

    int arow = tid >> 2;              // 0..63
    int acol = (tid & 3) * 4;         // 0,4,8,12
    int brow = tid >> 4;              // 0..15
    int bcol = (tid & 15) * 4;        // 0..60

    const float* Aptr = A + (size_t)(blockIdx.y * 64 + arow) * K + acol;
    bool avalid = (blockIdx.y * 64 + arow) < M;
    const float* Bptr = B + (size_t)brow * Nc + blockIdx.x * 64 + bcol;

    float acc[4][4];
#pragma unroll
    for (int i = 0; i < 4; i++)
#pragma unroll
        for (int j = 0; j < 4; j++) acc[i][j] = 0.f;

    for (int k0 = 0; k0 < K; k0 += 16) {
        float4 a = avalid ? *(const float4*)Aptr : make_float4(0.f, 0.f, 0.f, 0.f);
        float4 b = *(const float4*)Bptr;
        As[acol + 0][arow] = a.x;
        As[acol + 1][arow] = a.y;
        As[acol + 2][arow] = a.z;
        As[acol + 3][arow] = a.w;
        *(float4*)&Bs[brow][bcol] = b;
        __syncthreads();
#pragma unroll
        for (int k = 0; k < 16; k++) {
            float ra[4], rb[4];
#pragma unroll
            for (int i = 0; i < 4; i++) ra[i] = As[k][tr * 4 + i];
#pragma unroll
            for (int j = 0; j < 4; j++) rb[j] = Bs[k][tc * 4 + j];
#pragma unroll
            for (int i = 0; i < 4; i++)
#pragma unroll
                for (int j = 0; j < 4; j++) acc[i][j] += ra[i] * rb[j];
        }
        __syncthreads();
        Aptr += 16;
        Bptr += (size_t)16 * Nc;
    }

#pragma unroll
    for (int i = 0; i < 4; i++) {
        int r = rowC + i;
        if (r < M) {
            float4 v = make_float4(acc[i][0], acc[i][1], acc[i][2], acc[i][3]);
            *(float4*)&C[(size_t)r * Nc + colC] = v;
        }
    }
}

// ---------------- attention coefficients layer 1: el/er per (node, head) ----------------
__global__ void attn1_kernel(const float* __restrict__ al, const float* __restrict__ ar) {
    int w = (blockIdx.x * blockDim.x + threadIdx.x) >> 5;
    if (w >= NNODES) return;
    int lane = threadIdx.x & 31;
    const float* f = g_feat1 + (size_t)w * HD1;
#pragma unroll
    for (int h = 0; h < H1; h++) {
        float v = f[h * HID + lane];
        float pl = v * al[h * HID + lane];
        float pr = v * ar[h * HID + lane];
#pragma unroll
        for (int o = 16; o > 0; o >>= 1) {
            pl += __shfl_xor_sync(0xffffffffu, pl, o);
            pr += __shfl_xor_sync(0xffffffffu, pr, o);
        }
        if (lane == 0) {
            g_el1[w * H1 + h] = pl;
            g_er1[w * H1 + h] = pr;
        }
    }
}

// ---------------- attention coefficients layer 2 (single head, D=64) ----------------
__global__ void attn2_kernel(const float* __restrict__ al, const float* __restrict__ ar) {
    int w = (blockIdx.x * blockDim.x + threadIdx.x) >> 5;
    if (w >= NNODES) return;
    int lane = threadIdx.x & 31;
    const float* f = g_feat2 + (size_t)w * OUT_DIM;
    float v0 = f[lane], v1 = f[lane + 32];
    float pl = v0 * al[lane] + v1 * al[lane + 32];
    float pr = v0 * ar[lane] + v1 * ar[lane + 32];
#pragma unroll
    for (int o = 16; o > 0; o >>= 1) {
        pl += __shfl_xor_sync(0xffffffffu, pl, o);
        pr += __shfl_xor_sync(0xffffffffu, pr, o);
    }
    if (lane == 0) {
        g_el2[w] = pl;
        g_er2[w] = pr;
    }
}

// ---------------- CSR build ----------------
__global__ void zero_cnt_kernel() {
    int i = blockIdx.x * blockDim.x + threadIdx.x;
    if (i < NNODES) g_cnt[i] = 0;
}

__global__ void hist_kernel(const int* __restrict__ dst) {
    int e = blockIdx.x * blockDim.x + threadIdx.x;
    if (e < NEDGES) atomicAdd(&g_cnt[dst[e]], 1);
}

// single-block exclusive scan over g_cnt -> g_off, g_cur; g_off[NNODES]=total
__global__ void scan_kernel() {
    const int T = 1024;
    __shared__ int s[T];
    int tid = threadIdx.x;
    int carry = 0;
    for (int base = 0; base < NNODES; base += T * 4) {
        int idx = base + tid * 4;
        int v0 = 0, v1 = 0, v2 = 0, v3 = 0;
        if (idx + 3 < NNODES) {
            int4 t = *(const int4*)&g_cnt[idx];
            v0 = t.x; v1 = t.y; v2 = t.z; v3 = t.w;
        } else {
            if (idx + 0 < NNODES) v0 = g_cnt[idx + 0];
            if (idx + 1 < NNODES) v1 = g_cnt[idx + 1];
            if (idx + 2 < NNODES) v2 = g_cnt[idx + 2];
            if (idx + 3 < NNODES) v3 = g_cnt[idx + 3];
        }
        int tsum = v0 + v1 + v2 + v3;
        s[tid] = tsum;
        __syncthreads();
        for (int o = 1; o < T; o <<= 1) {
            int t = (tid >= o) ? s[tid - o] : 0;
            __syncthreads();
            s[tid] += t;
            __syncthreads();
        }
        int excl = s[tid] - tsum;
        int total = s[T - 1];
        int p = carry + excl;
        if (idx + 0 < NNODES) { g_off[idx + 0] = p;              g_cur[idx + 0] = p; }
        if (idx + 1 < NNODES) { g_off[idx + 1] = p + v0;         g_cur[idx + 1] = p + v0; }
        if (idx + 2 < NNODES) { g_off[idx + 2] = p + v0 + v1;    g_cur[idx + 2] = p + v0 + v1; }
        if (idx + 3 < NNODES) { g_off[idx + 3] = p + v0 + v1 + v2; g_cur[idx + 3] = p + v0 + v1 + v2; }
        carry += total;
        __syncthreads();
    }
    if (tid == 0) g_off[NNODES] = carry;
}

__global__ void scatter_kernel(const int* __restrict__ src, const int* __restrict__ dst) {
    int e = blockIdx.x * blockDim.x + threadIdx.x;
    if (e < NEDGES) {
        int p = atomicAdd(&g_cur[dst[e]], 1);
        g_csr_src[p] = src[e];
    }
}

// ---------------- layer 1 aggregation: warp per dst node ----------------
// lane -> head hh = lane>>2, dim chunk db = (lane&3)*8 (8 dims via two float4)
__global__ void agg1_kernel(const float* __restrict__ b1) {
    int n = (blockIdx.x * blockDim.x + threadIdx.x) >> 5;
    if (n >= NNODES) return;
    int lane = threadIdx.x & 31;
    int hh = lane >> 2;
    int db = (lane & 3) * 8;

    float ern = g_er1[n * H1 + hh];
    float wsum = 0.f;
    float4 a0 = make_float4(0.f, 0.f, 0.f, 0.f);
    float4 a1 = make_float4(0.f, 0.f, 0.f, 0.f);

    int beg = g_off[n], end = g_off[n + 1];
    for (int e = beg; e < end; e++) {
        int s = g_csr_src[e];
        float x = g_el1[s * H1 + hh] + ern;
        x = fmaxf(x, 0.2f * x);          // leaky_relu(0.2)
        float wgt = __expf(x);
        wsum += wgt;
        const float4* fp = (const float4*)(g_feat1 + (size_t)s * HD1 + hh * HID + db);
        float4 f0 = fp[0], f1 = fp[1];
        a0.x += wgt * f0.x; a0.y += wgt * f0.y; a0.z += wgt * f0.z; a0.w += wgt * f0.w;
        a1.x += wgt * f1.x; a1.y += wgt * f1.y; a1.z += wgt * f1.z; a1.w += wgt * f1.w;
    }

    float inv = 1.f / wsum;
    float* o = g_h1 + (size_t)n * HD1 + hh * HID + db;
    const float* bp = b1 + hh * HID + db;
    float r[8] = { a0.x, a0.y, a0.z, a0.w, a1.x, a1.y, a1.z, a1.w };
#pragma unroll
    for (int k = 0; k < 8; k++) {
        float v = r[k] * inv + bp[k];
        o[k] = v > 0.f ? v : (__expf(v) - 1.f);   // ELU
    }
}

// ---------------- layer 2 aggregation: warp per dst node, D=64, 1 head ----------------
__global__ void agg2_kernel(const float* __restrict__ b2, float* __restrict__ out) {
    int n = (blockIdx.x * blockDim.x + threadIdx.x) >> 5;
    if (n >= NNODES) return;
    int lane = threadIdx.x & 31;

    float ern = g_er2[n];
    float wsum = 0.f;
    float a0 = 0.f, a1 = 0.f;

    int beg = g_off[n], end = g_off[n + 1];
    for (int e = beg; e < end; e++) {
        int s = g_csr_src[e];
        float x = g_el2[s] + ern;
        x = fmaxf(x, 0.2f * x);
        float wgt = __expf(x);
        wsum += wgt;
        float2 f = *(const float2*)(g_feat2 + (size_t)s * OUT_DIM + lane * 2);
        a0 += wgt * f.x;
        a1 += wgt * f.y;
    }

    float inv = 1.f / wsum;
    out[(size_t)n * OUT_DIM + lane * 2 + 0] = a0 * inv + b2[lane * 2 + 0];
    out[(size_t)n * OUT_DIM + lane * 2 + 1] = a1 * inv + b2[lane * 2 + 1];
}

// ---------------- launch ----------------
extern "C" void kernel_launch(void* const* d_in, const int* in_sizes, int n_in,
                              void* d_out, int out_size) {
    const float* h   = (const float*)d_in[0];
    const float* W1  = (const float*)d_in[1];
    const float* al1 = (const float*)d_in[2];
    const float* ar1 = (const float*)d_in[3];
    const float* b1  = (const float*)d_in[4];
    const float* W2  = (const float*)d_in[5];
    const float* al2 = (const float*)d_in[6];
    const float* ar2 = (const float*)d_in[7];
    const float* b2  = (const float*)d_in[8];
    const int*   src = (const int*)d_in[9];
    const int*   dst = (const int*)d_in[10];
    float* out = (float*)d_out;

    float* feat1; cudaGetSymbolAddress((void**)&feat1, g_feat1);
    float* h1p;   cudaGetSymbolAddress((void**)&h1p, g_h1);
    float* feat2; cudaGetSymbolAddress((void**)&feat2, g_feat2);

    const int nwarpblocks = (NNODES * 32 + 255) / 256;   // 6250
    const int eblocks = (NEDGES + 255) / 256;

    // CSR build (independent of GEMM, but serialized on default stream — fine)
    zero_cnt_kernel<<<(NNODES + 255) / 256, 256>>>();
    hist_kernel<<<eblocks, 256>>>(dst);
    scan_kernel<<<1, 1024>>>();
    scatter_kernel<<<eblocks, 256>>>(src, dst);

    // layer 1
    {
        dim3 grid(HD1 / 64, (NNODES + 63) / 64);
        sgemm_kernel<<<grid, 256>>>(h, W1, feat1, NNODES, HD1, IN_DIM);
    }
    attn1_kernel<<<nwarpblocks, 256>>>(al1, ar1);
    agg1_kernel<<<nwarpblocks, 256>>>(b1);

    // layer 2
    {
        dim3 grid(OUT_DIM / 64, (NNODES + 63) / 64);
        sgemm_kernel<<<grid, 256>>>(h1p, W2, feat2, NNODES, OUT_DIM, HD1);
    }
    attn2_kernel<<<nwarpblocks, 256>>>(al2, ar2);
    agg2_kernel<<<nwarpblocks, 256>>>(b2, out);
}

// round 2
// speedup vs baseline: 1.0812x; 1.0812x over previous
#include <cuda_runtime.h>
#include <cuda_bf16.h>
#include <cstdint>

#define NNODES 50000
#define NEDGES 850000
#define IN_DIM 256
#define HID 32
#define H1 8
#define OUT_DIM 64
#define HD1 (H1*HID)   // 256

// ---------------- scratch (static device globals; no allocation) ----------------
__device__ __align__(16) float g_feat1[NNODES * HD1];     // 51.2 MB
__device__ __align__(16) float g_h1[NNODES * HD1];        // 51.2 MB
__device__ __align__(16) float g_feat2[NNODES * OUT_DIM]; // 12.8 MB
__device__ __align__(16) float g_el1[NNODES * H1];
__device__ __align__(16) float g_er1[NNODES * H1];
__device__ __align__(16) float g_el2[NNODES];
__device__ __align__(16) float g_er2[NNODES];
__device__ __align__(16) int   g_cnt[NNODES];
__device__ __align__(16) int   g_off[NNODES + 1];
__device__ __align__(16) int   g_cur[NNODES];
__device__ __align__(16) int   g_csr_src[NEDGES];

// ---------------- tf32 helpers ----------------
__device__ __forceinline__ uint32_t f2tf32(float x) {
    uint32_t r;
    asm("cvt.rna.tf32.f32 %0, %1;" : "=r"(r) : "f"(x));
    return r;
}

__device__ __forceinline__ void mma_tf32(float c[4], const uint32_t a[4], const uint32_t b[2]) {
    asm("mma.sync.aligned.m16n8k8.row.col.f32.tf32.tf32.f32 "
        "{%0,%1,%2,%3}, {%4,%5,%6,%7}, {%8,%9}, {%0,%1,%2,%3};"
        : "+f"(c[0]), "+f"(c[1]), "+f"(c[2]), "+f"(c[3])
        : "r"(a[0]), "r"(a[1]), "r"(a[2]), "r"(a[3]), "r"(b[0]), "r"(b[1]));
}

// ---------------- tf32 tensor-core GEMM: C[M,Nc] = A[M,K] @ B[K,Nc] ----------------
// BM=128, BN=64, BK=16, 256 threads (8 warps in 4x2), warp tile 32x32 via m16n8k8.
// If al != nullptr: fused attention epilogue (layer1, head width = 32 cols = warp n-tile):
//   el[row*H1+head] = sum_col C*al ; er likewise. Head index = globalCol/32.
#define BM 128
#define BN 64
#define BK 16
#define AS_STRIDE 20   // BK + 4 -> conflict-free A-frag loads
#define BS_STRIDE 72   // BN + 8 -> conflict-free B-frag loads

__global__ __launch_bounds__(256) void tf32_gemm_kernel(
    const float* __restrict__ A, const float* __restrict__ B, float* __restrict__ C,
    int M, int K, int Nc,
    const float* __restrict__ al, const float* __restrict__ ar)
{
    __shared__ uint32_t As[BM * AS_STRIDE];
    __shared__ uint32_t Bs[BK * BS_STRIDE];

    int tid = threadIdx.x;
    int lane = tid & 31;
    int warp = tid >> 5;
    int groupID = lane >> 2;
    int tig = lane & 3;

    int warpRow = (warp & 3) * 32;
    int warpCol = (warp >> 2) * 32;

    int blockRow = blockIdx.y * BM;
    int blockCol = blockIdx.x * BN;

    int arow = tid >> 2;           // 0..63
    int acol = (tid & 3) * 4;      // 0,4,8,12
    int brow = tid >> 4;           // 0..15
    int bcol = (tid & 15) * 4;     // 0..60

    const float* Ap0 = A + (size_t)(blockRow + arow) * K + acol;
    const float* Ap1 = A + (size_t)(blockRow + arow + 64) * K + acol;
    bool av0 = (blockRow + arow) < M;
    bool av1 = (blockRow + arow + 64) < M;
    const float* Bp = B + (size_t)brow * Nc + blockCol + bcol;

    float acc[2][4][4];
#pragma unroll
    for (int mi = 0; mi < 2; mi++)
#pragma unroll
        for (int ni = 0; ni < 4; ni++)
#pragma unroll
            for (int c = 0; c < 4; c++) acc[mi][ni][c] = 0.f;

    for (int k0 = 0; k0 < K; k0 += BK) {
        float4 a0 = av0 ? *(const float4*)Ap0 : make_float4(0.f,0.f,0.f,0.f);
        float4 a1 = av1 ? *(const float4*)Ap1 : make_float4(0.f,0.f,0.f,0.f);
        float4 b  = *(const float4*)Bp;

        uint32_t* asp0 = &As[arow * AS_STRIDE + acol];
        asp0[0] = f2tf32(a0.x); asp0[1] = f2tf32(a0.y);
        asp0[2] = f2tf32(a0.z); asp0[3] = f2tf32(a0.w);
        uint32_t* asp1 = &As[(arow + 64) * AS_STRIDE + acol];
        asp1[0] = f2tf32(a1.x); asp1[1] = f2tf32(a1.y);
        asp1[2] = f2tf32(a1.z); asp1[3] = f2tf32(a1.w);
        uint32_t* bsp = &Bs[brow * BS_STRIDE + bcol];
        bsp[0] = f2tf32(b.x); bsp[1] = f2tf32(b.y);
        bsp[2] = f2tf32(b.z); bsp[3] = f2tf32(b.w);
        __syncthreads();

#pragma unroll
        for (int kk = 0; kk < BK; kk += 8) {
            uint32_t af[2][4];
#pragma unroll
            for (int mi = 0; mi < 2; mi++) {
                int r = warpRow + mi * 16 + groupID;
                af[mi][0] = As[r * AS_STRIDE + kk + tig];
                af[mi][1] = As[(r + 8) * AS_STRIDE + kk + tig];
                af[mi][2] = As[r * AS_STRIDE + kk + tig + 4];
                af[mi][3] = As[(r + 8) * AS_STRIDE + kk + tig + 4];
            }
            uint32_t bf[4][2];
#pragma unroll
            for (int ni = 0; ni < 4; ni++) {
                int c = warpCol + ni * 8 + groupID;
                bf[ni][0] = Bs[(kk + tig) * BS_STRIDE + c];
                bf[ni][1] = Bs[(kk + tig + 4) * BS_STRIDE + c];
            }
#pragma unroll
            for (int mi = 0; mi < 2; mi++)
#pragma unroll
                for (int ni = 0; ni < 4; ni++)
                    mma_tf32(acc[mi][ni], af[mi], bf[ni]);
        }
        __syncthreads();
        Ap0 += BK; Ap1 += BK; Bp += (size_t)BK * Nc;
    }

    // store C
#pragma unroll
    for (int mi = 0; mi < 2; mi++) {
        int r0 = blockRow + warpRow + mi * 16 + groupID;
        int r1 = r0 + 8;
#pragma unroll
        for (int ni = 0; ni < 4; ni++) {
            int c = blockCol + warpCol + ni * 8 + tig * 2;
            if (r0 < M) *(float2*)&C[(size_t)r0 * Nc + c] = make_float2(acc[mi][ni][0], acc[mi][ni][1]);
            if (r1 < M) *(float2*)&C[(size_t)r1 * Nc + c] = make_float2(acc[mi][ni][2], acc[mi][ni][3]);
        }
    }

    // fused layer-1 attention coefficients: one warp n-tile == one 32-wide head
    if (al != nullptr) {
        int head = (blockCol + warpCol) >> 5;
#pragma unroll
        for (int mi = 0; mi < 2; mi++) {
            float plA = 0.f, prA = 0.f, plB = 0.f, prB = 0.f;
#pragma unroll
            for (int ni = 0; ni < 4; ni++) {
                int c = blockCol + warpCol + ni * 8 + tig * 2;
                float al0 = al[c], al1v = al[c + 1];
                float ar0 = ar[c], ar1v = ar[c + 1];
                plA += acc[mi][ni][0] * al0 + acc[mi][ni][1] * al1v;
                prA += acc[mi][ni][0] * ar0 + acc[mi][ni][1] * ar1v;
                plB += acc[mi][ni][2] * al0 + acc[mi][ni][3] * al1v;
                prB += acc[mi][ni][2] * ar0 + acc[mi][ni][3] * ar1v;
            }
#pragma unroll
            for (int o = 1; o <= 2; o <<= 1) {
                plA += __shfl_xor_sync(0xffffffffu, plA, o);
                prA += __shfl_xor_sync(0xffffffffu, prA, o);
                plB += __shfl_xor_sync(0xffffffffu, plB, o);
                prB += __shfl_xor_sync(0xffffffffu, prB, o);
            }
            if (tig == 0) {
                int r0 = blockRow + warpRow + mi * 16 + groupID;
                int r1 = r0 + 8;
                if (r0 < M) { g_el1[r0 * H1 + head] = plA; g_er1[r0 * H1 + head] = prA; }
                if (r1 < M) { g_el1[r1 * H1 + head] = plB; g_er1[r1 * H1 + head] = prB; }
            }
        }
    }
}

// ---------------- attention coefficients layer 2 (single head, D=64) ----------------
__global__ void attn2_kernel(const float* __restrict__ al, const float* __restrict__ ar) {
    int w = (blockIdx.x * blockDim.x + threadIdx.x) >> 5;
    if (w >= NNODES) return;
    int lane = threadIdx.x & 31;
    const float* f = g_feat2 + (size_t)w * OUT_DIM;
    float v0 = f[lane], v1 = f[lane + 32];
    float pl = v0 * al[lane] + v1 * al[lane + 32];
    float pr = v0 * ar[lane] + v1 * ar[lane + 32];
#pragma unroll
    for (int o = 16; o > 0; o >>= 1) {
        pl += __shfl_xor_sync(0xffffffffu, pl, o);
        pr += __shfl_xor_sync(0xffffffffu, pr, o);
    }
    if (lane == 0) {
        g_el2[w] = pl;
        g_er2[w] = pr;
    }
}

// ---------------- CSR build ----------------
__global__ void zero_cnt_kernel() {
    int i = blockIdx.x * blockDim.x + threadIdx.x;
    if (i < NNODES) g_cnt[i] = 0;
}

__global__ void hist_kernel(const int* __restrict__ dst) {
    int e = blockIdx.x * blockDim.x + threadIdx.x;
    if (e < NEDGES) atomicAdd(&g_cnt[dst[e]], 1);
}

// single-block exclusive scan over g_cnt -> g_off, g_cur; g_off[NNODES]=total
__global__ void scan_kernel() {
    const int T = 1024;
    __shared__ int s[T];
    int tid = threadIdx.x;
    int carry = 0;
    for (int base = 0; base < NNODES; base += T * 4) {
        int idx = base + tid * 4;
        int v0 = 0, v1 = 0, v2 = 0, v3 = 0;
        if (idx + 3 < NNODES) {
            int4 t = *(const int4*)&g_cnt[idx];
            v0 = t.x; v1 = t.y; v2 = t.z; v3 = t.w;
        } else {
            if (idx + 0 < NNODES) v0 = g_cnt[idx + 0];
            if (idx + 1 < NNODES) v1 = g_cnt[idx + 1];
            if (idx + 2 < NNODES) v2 = g_cnt[idx + 2];
            if (idx + 3 < NNODES) v3 = g_cnt[idx + 3];
        }
        int tsum = v0 + v1 + v2 + v3;
        s[tid] = tsum;
        __syncthreads();
        for (int o = 1; o < T; o <<= 1) {
            int t = (tid >= o) ? s[tid - o] : 0;
            __syncthreads();
            s[tid] += t;
            __syncthreads();
        }
        int excl = s[tid] - tsum;
        int total = s[T - 1];
        int p = carry + excl;
        if (idx + 0 < NNODES) { g_off[idx + 0] = p;                g_cur[idx + 0] = p; }
        if (idx + 1 < NNODES) { g_off[idx + 1] = p + v0;           g_cur[idx + 1] = p + v0; }
        if (idx + 2 < NNODES) { g_off[idx + 2] = p + v0 + v1;      g_cur[idx + 2] = p + v0 + v1; }
        if (idx + 3 < NNODES) { g_off[idx + 3] = p + v0 + v1 + v2; g_cur[idx + 3] = p + v0 + v1 + v2; }
        carry += total;
        __syncthreads();
    }
    if (tid == 0) g_off[NNODES] = carry;
}

__global__ void scatter_kernel(const int* __restrict__ src, const int* __restrict__ dst) {
    int e = blockIdx.x * blockDim.x + threadIdx.x;
    if (e < NEDGES) {
        int p = atomicAdd(&g_cur[dst[e]], 1);
        g_csr_src[p] = src[e];
    }
}

// ---------------- layer 1 aggregation: warp per dst node ----------------
__global__ void agg1_kernel(const float* __restrict__ b1) {
    int n = (blockIdx.x * blockDim.x + threadIdx.x) >> 5;
    if (n >= NNODES) return;
    int lane = threadIdx.x & 31;
    int hh = lane >> 2;
    int db = (lane & 3) * 8;

    float ern = g_er1[n * H1 + hh];
    float wsum = 0.f;
    float4 a0 = make_float4(0.f, 0.f, 0.f, 0.f);
    float4 a1 = make_float4(0.f, 0.f, 0.f, 0.f);

    int beg = g_off[n], end = g_off[n + 1];
    for (int e = beg; e < end; e++) {
        int s = g_csr_src[e];
        float x = g_el1[s * H1 + hh] + ern;
        x = fmaxf(x, 0.2f * x);          // leaky_relu(0.2)
        float wgt = __expf(x);
        wsum += wgt;
        const float4* fp = (const float4*)(g_feat1 + (size_t)s * HD1 + hh * HID + db);
        float4 f0 = fp[0], f1 = fp[1];
        a0.x += wgt * f0.x; a0.y += wgt * f0.y; a0.z += wgt * f0.z; a0.w += wgt * f0.w;
        a1.x += wgt * f1.x; a1.y += wgt * f1.y; a1.z += wgt * f1.z; a1.w += wgt * f1.w;
    }

    float inv = 1.f / wsum;
    float* o = g_h1 + (size_t)n * HD1 + hh * HID + db;
    const float* bp = b1 + hh * HID + db;
    float r[8] = { a0.x, a0.y, a0.z, a0.w, a1.x, a1.y, a1.z, a1.w };
#pragma unroll
    for (int k = 0; k < 8; k++) {
        float v = r[k] * inv + bp[k];
        o[k] = v > 0.f ? v : (__expf(v) - 1.f);   // ELU
    }
}

// ---------------- layer 2 aggregation: warp per dst node, D=64, 1 head ----------------
__global__ void agg2_kernel(const float* __restrict__ b2, float* __restrict__ out) {
    int n = (blockIdx.x * blockDim.x + threadIdx.x) >> 5;
    if (n >= NNODES) return;
    int lane = threadIdx.x & 31;

    float ern = g_er2[n];
    float wsum = 0.f;
    float a0 = 0.f, a1 = 0.f;

    int beg = g_off[n], end = g_off[n + 1];
    for (int e = beg; e < end; e++) {
        int s = g_csr_src[e];
        float x = g_el2[s] + ern;
        x = fmaxf(x, 0.2f * x);
        float wgt = __expf(x);
        wsum += wgt;
        float2 f = *(const float2*)(g_feat2 + (size_t)s * OUT_DIM + lane * 2);
        a0 += wgt * f.x;
        a1 += wgt * f.y;
    }

    float inv = 1.f / wsum;
    out[(size_t)n * OUT_DIM + lane * 2 + 0] = a0 * inv + b2[lane * 2 + 0];
    out[(size_t)n * OUT_DIM + lane * 2 + 1] = a1 * inv + b2[lane * 2 + 1];
}

// ---------------- launch ----------------
extern "C" void kernel_launch(void* const* d_in, const int* in_sizes, int n_in,
                              void* d_out, int out_size) {
    const float* h   = (const float*)d_in[0];
    const float* W1  = (const float*)d_in[1];
    const float* al1 = (const float*)d_in[2];
    const float* ar1 = (const float*)d_in[3];
    const float* b1  = (const float*)d_in[4];
    const float* W2  = (const float*)d_in[5];
    const float* al2 = (const float*)d_in[6];
    const float* ar2 = (const float*)d_in[7];
    const float* b2  = (const float*)d_in[8];
    const int*   src = (const int*)d_in[9];
    const int*   dst = (const int*)d_in[10];
    float* out = (float*)d_out;

    float* feat1; cudaGetSymbolAddress((void**)&feat1, g_feat1);
    float* h1p;   cudaGetSymbolAddress((void**)&h1p, g_h1);
    float* feat2; cudaGetSymbolAddress((void**)&feat2, g_feat2);

    static cudaStream_t s_csr = nullptr;
    static cudaEvent_t ev_fork = nullptr, ev_join = nullptr;
    if (s_csr == nullptr) {
        cudaStreamCreateWithFlags(&s_csr, cudaStreamNonBlocking);
        cudaEventCreateWithFlags(&ev_fork, cudaEventDisableTiming);
        cudaEventCreateWithFlags(&ev_join, cudaEventDisableTiming);
    }

    const int nwarpblocks = (NNODES * 32 + 255) / 256;   // 6250
    const int eblocks = (NEDGES + 255) / 256;

    // fork: CSR build runs concurrently with GEMM1
    cudaEventRecord(ev_fork, 0);
    cudaStreamWaitEvent(s_csr, ev_fork, 0);
    zero_cnt_kernel<<<(NNODES + 255) / 256, 256, 0, s_csr>>>();
    hist_kernel<<<eblocks, 256, 0, s_csr>>>(dst);
    scan_kernel<<<1, 1024, 0, s_csr>>>();
    scatter_kernel<<<eblocks, 256, 0, s_csr>>>(src, dst);
    cudaEventRecord(ev_join, s_csr);

    // layer 1: GEMM (tf32 tensor cores) with fused el/er epilogue
    {
        dim3 grid(HD1 / BN, (NNODES + BM - 1) / BM);
        tf32_gemm_kernel<<<grid, 256>>>(h, W1, feat1, NNODES, IN_DIM, HD1, al1, ar1);
    }
    cudaStreamWaitEvent(0, ev_join, 0);   // join before aggregation
    agg1_kernel<<<nwarpblocks, 256>>>(b1);

    // layer 2
    {
        dim3 grid(OUT_DIM / BN, (NNODES + BM - 1) / BM);
        tf32_gemm_kernel<<<grid, 256>>>(h1p, W2, feat2, NNODES, HD1, OUT_DIM, nullptr, nullptr);
    }
    attn2_kernel<<<nwarpblocks, 256>>>(al2, ar2);
    agg2_kernel<<<nwarpblocks, 256>>>(b2, out);
}

// round 5
// speedup vs baseline: 1.1298x; 1.0450x over previous
#include <cuda_runtime.h>
#include <cuda_fp16.h>
#include <cstdint>

#define NNODES 50000
#define NEDGES 850000
#define IN_DIM 256
#define HID 32
#define H1 8
#define OUT_DIM 64
#define HD1 (H1*HID)   // 256
#define KDIM 256

// ---------------- scratch ----------------
__device__ __align__(16) __half g_feat1h[NNODES * HD1];   // 25.6 MB fp16
__device__ __align__(16) float  g_h1[NNODES * HD1];       // 51.2 MB
__device__ __align__(16) float  g_feat2[NNODES * OUT_DIM];
__device__ __align__(16) float  g_el1[NNODES * H1];
__device__ __align__(16) float  g_er1[NNODES * H1];
__device__ __align__(16) float  g_el2[NNODES];
__device__ __align__(16) float  g_er2[NNODES];
__device__ __align__(16) int    g_cnt[NNODES];
__device__ __align__(16) int    g_off[NNODES + 1];
__device__ __align__(16) int    g_cur[NNODES];
__device__ __align__(16) int    g_csr_src[NEDGES];

// packed f32x2 FMA: d.lo += a.lo*b.lo ; d.hi += a.hi*b.hi
#define FMA_X2(d, a, b) \
    asm("fma.rn.f32x2 %0, %1, %2, %0;" : "+l"(d) : "l"(a), "l"(b))

__device__ __forceinline__ uint32_t h2_bits(__half2 h) {
    uint32_t u;
    memcpy(&u, &h, 4);
    return u;
}

// ---------------- packed-fp32 GEMM + fused attention epilogue ----------------
// C[M, Nc-tile] : rows [by*128, +128), cols [bx*64, +64). K = 256 for both layers.
// LAYER 1: C -> __half feat1 (row stride 256), el1/er1 per 32-col head.
// LAYER 2: C -> float feat2 (row stride 64), el2/er2 whole row.
#define BMT 128
#define BNT 64
#define BKT 16
#define AS2_STRIDE (2*BMT + 8)   // 264 floats
#define BS_STRIDE  (BNT + 4)     // 68 floats

template <int LAYER>
__global__ __launch_bounds__(128) void pgemm_kernel(
    const float* __restrict__ A, int M, int Nc,
    const float* __restrict__ B,          // [K=256][Nc] row-major
    void* __restrict__ Cout,
    const float* __restrict__ al, const float* __restrict__ ar)
{
    __shared__ float As2[BKT][AS2_STRIDE];   // duplicated: value of row r at [2r],[2r+1]
    __shared__ float Bs[BKT][BS_STRIDE];

    const int tid = threadIdx.x;
    const int tr = tid >> 3;        // 0..15  (8 rows each)
    const int tc = tid & 7;         // 0..7   (8 cols each)
    const int blockRow = blockIdx.y * BMT;
    const int colbase = blockIdx.x * BNT;

    unsigned long long acc[8][4];
#pragma unroll
    for (int i = 0; i < 8; i++)
#pragma unroll
        for (int j = 0; j < 4; j++) acc[i][j] = 0ull;

    const int gr = blockRow + tid;
    const bool arowv = gr < M;
    const float* ap = A + (size_t)gr * KDIM;

    for (int k0 = 0; k0 < KDIM; k0 += BKT) {
        // ---- A: thread owns row `tid`, 16 k values, stored duplicated ----
        float4 av[4];
        if (arowv) {
#pragma unroll
            for (int q = 0; q < 4; q++) av[q] = *(const float4*)(ap + k0 + q * 4);
        } else {
#pragma unroll
            for (int q = 0; q < 4; q++) av[q] = make_float4(0.f, 0.f, 0.f, 0.f);
        }
#pragma unroll
        for (int q = 0; q < 4; q++) {
            const float* vv = (const float*)&av[q];
#pragma unroll
            for (int e = 0; e < 4; e++) {
                float x = vv[e];
                *(float2*)&As2[q * 4 + e][2 * tid] = make_float2(x, x);
            }
        }
        // ---- B: 16 x 64 floats, 128 threads x 2 float4 ----
#pragma unroll
        for (int q = 0; q < 2; q++) {
            int i = tid * 2 + q;
            int row = i >> 4, c4 = (i & 15) * 4;
            float4 v = *(const float4*)&B[(size_t)(k0 + row) * Nc + colbase + c4];
            *(float4*)&Bs[row][c4] = v;
        }
        __syncthreads();

#pragma unroll
        for (int kk = 0; kk < BKT; kk++) {
            unsigned long long a8[8], b4[4];
#pragma unroll
            for (int q = 0; q < 4; q++) {
                ulonglong2 t = *(const ulonglong2*)&As2[kk][2 * (tr * 8) + 4 * q];
                a8[2 * q] = t.x; a8[2 * q + 1] = t.y;
            }
#pragma unroll
            for (int q = 0; q < 2; q++) {
                ulonglong2 t = *(const ulonglong2*)&Bs[kk][tc * 8 + 4 * q];
                b4[2 * q] = t.x; b4[2 * q + 1] = t.y;
            }
#pragma unroll
            for (int i = 0; i < 8; i++)
#pragma unroll
                for (int j = 0; j < 4; j++)
                    FMA_X2(acc[i][j], a8[i], b4[j]);
        }
        __syncthreads();
    }

    // ---- epilogue: store C + fused el/er ----
    const int c0 = colbase + tc * 8;
    float alr[8], arr[8];
#pragma unroll
    for (int j = 0; j < 8; j++) { alr[j] = al[c0 + j]; arr[j] = ar[c0 + j]; }

    float elp[8], erp[8];
#pragma unroll
    for (int i = 0; i < 8; i++) {
        const int r = blockRow + tr * 8 + i;
        float c[8];
#pragma unroll
        for (int j = 0; j < 4; j++) {
            uint2 u = *(uint2*)&acc[i][j];
            c[2 * j] = __uint_as_float(u.x);
            c[2 * j + 1] = __uint_as_float(u.y);
        }
        float el = 0.f, er = 0.f;
#pragma unroll
        for (int j = 0; j < 8; j++) { el += c[j] * alr[j]; er += c[j] * arr[j]; }
        elp[i] = el; erp[i] = er;

        if (r < M) {
            if (LAYER == 1) {
                __half2 p0 = __floats2half2_rn(c[0], c[1]);
                __half2 p1 = __floats2half2_rn(c[2], c[3]);
                __half2 p2 = __floats2half2_rn(c[4], c[5]);
                __half2 p3 = __floats2half2_rn(c[6], c[7]);
                uint4 w = make_uint4(h2_bits(p0), h2_bits(p1), h2_bits(p2), h2_bits(p3));
                *(uint4*)&g_feat1h[(size_t)r * HD1 + c0] = w;
            } else {
                float* crow = (float*)Cout + (size_t)r * OUT_DIM + c0;
                *(float4*)crow = make_float4(c[0], c[1], c[2], c[3]);
                *(float4*)(crow + 4) = make_float4(c[4], c[5], c[6], c[7]);
            }
        }
    }

    // reduce el/er across threads sharing rows (same tr)
    if (LAYER == 1) {
        // reduce over tc within half (4 threads), head = bx*2 + (tc>>2)
#pragma unroll
        for (int i = 0; i < 8; i++) {
#pragma unroll
            for (int o = 1; o <= 2; o <<= 1) {
                elp[i] += __shfl_xor_sync(0xffffffffu, elp[i], o);
                erp[i] += __shfl_xor_sync(0xffffffffu, erp[i], o);
            }
        }
        if ((tc & 3) == 0) {
            int head = blockIdx.x * 2 + (tc >> 2);
#pragma unroll
            for (int i = 0; i < 8; i++) {
                int r = blockRow + tr * 8 + i;
                if (r < M) {
                    g_el1[r * H1 + head] = elp[i];
                    g_er1[r * H1 + head] = erp[i];
                }
            }
        }
    } else {
        // reduce over all 8 tc
#pragma unroll
        for (int i = 0; i < 8; i++) {
#pragma unroll
            for (int o = 1; o <= 4; o <<= 1) {
                elp[i] += __shfl_xor_sync(0xffffffffu, elp[i], o);
                erp[i] += __shfl_xor_sync(0xffffffffu, erp[i], o);
            }
        }
        if (tc == 0) {
#pragma unroll
            for (int i = 0; i < 8; i++) {
                int r = blockRow + tr * 8 + i;
                if (r < M) { g_el2[r] = elp[i]; g_er2[r] = erp[i]; }
            }
        }
    }
}

// ---------------- CSR build ----------------
__global__ void zero_cnt_kernel() {
    int i = blockIdx.x * blockDim.x + threadIdx.x;
    if (i < NNODES) g_cnt[i] = 0;
}

__global__ void hist_kernel(const int* __restrict__ dst) {
    int e = blockIdx.x * blockDim.x + threadIdx.x;
    if (e < NEDGES) atomicAdd(&g_cnt[dst[e]], 1);
}

__global__ void scan_kernel() {
    __shared__ int warpsum[32];
    int tid = threadIdx.x, lane = tid & 31, wid = tid >> 5;
    int carry = 0;
    for (int base = 0; base < NNODES; base += 4096) {
        int idx = base + tid * 4;
        int v0 = 0, v1 = 0, v2 = 0, v3 = 0;
        if (idx + 3 < NNODES) {
            int4 t = *(const int4*)&g_cnt[idx];
            v0 = t.x; v1 = t.y; v2 = t.z; v3 = t.w;
        } else {
            if (idx + 0 < NNODES) v0 = g_cnt[idx + 0];
            if (idx + 1 < NNODES) v1 = g_cnt[idx + 1];
            if (idx + 2 < NNODES) v2 = g_cnt[idx + 2];
            if (idx + 3 < NNODES) v3 = g_cnt[idx + 3];
        }
        int tsum = v0 + v1 + v2 + v3;
        int x = tsum;
#pragma unroll
        for (int o = 1; o < 32; o <<= 1) {
            int t = __shfl_up_sync(0xffffffffu, x, o);
            if (lane >= o) x += t;
        }
        if (lane == 31) warpsum[wid] = x;
        __syncthreads();
        if (wid == 0) {
            int w = warpsum[lane];
#pragma unroll
            for (int o = 1; o < 32; o <<= 1) {
                int t = __shfl_up_sync(0xffffffffu, w, o);
                if (lane >= o) w += t;
            }
            warpsum[lane] = w;
        }
        __syncthreads();
        int wexcl = (wid == 0) ? 0 : warpsum[wid - 1];
        int total = warpsum[31];
        int p = carry + wexcl + x - tsum;
        if (idx + 0 < NNODES) { g_off[idx + 0] = p;                g_cur[idx + 0] = p; }
        if (idx + 1 < NNODES) { g_off[idx + 1] = p + v0;           g_cur[idx + 1] = p + v0; }
        if (idx + 2 < NNODES) { g_off[idx + 2] = p + v0 + v1;      g_cur[idx + 2] = p + v0 + v1; }
        if (idx + 3 < NNODES) { g_off[idx + 3] = p + v0 + v1 + v2; g_cur[idx + 3] = p + v0 + v1 + v2; }
        carry += total;
        __syncthreads();
    }
    if (tid == 0) g_off[NNODES] = carry;
}

__global__ void scatter_kernel(const int* __restrict__ src, const int* __restrict__ dst) {
    int e = blockIdx.x * blockDim.x + threadIdx.x;
    if (e < NEDGES) {
        int p = atomicAdd(&g_cur[dst[e]], 1);
        g_csr_src[p] = src[e];
    }
}

// ---------------- layer 1 aggregation: warp per dst node (fp16 feats) ----------------
__global__ void agg1_kernel(const float* __restrict__ b1) {
    int n = (blockIdx.x * blockDim.x + threadIdx.x) >> 5;
    if (n >= NNODES) return;
    int lane = threadIdx.x & 31;
    int hh = lane >> 2;
    int db = (lane & 3) * 8;     // 8 half elements

    float ern = g_er1[n * H1 + hh];
    float wsum = 0.f;
    float a[8];
#pragma unroll
    for (int k = 0; k < 8; k++) a[k] = 0.f;

    int beg = g_off[n], end = g_off[n + 1];
    for (int e = beg; e < end; e++) {
        int s = g_csr_src[e];
        float x = g_el1[s * H1 + hh] + ern;
        x = fmaxf(x, 0.2f * x);          // leaky_relu(0.2)
        float wgt = __expf(x);
        wsum += wgt;
        uint4 hv = *(const uint4*)(g_feat1h + (size_t)s * HD1 + hh * HID + db);
        const __half2* hp = (const __half2*)&hv;
        float2 f0 = __half22float2(hp[0]);
        float2 f1 = __half22float2(hp[1]);
        float2 f2 = __half22float2(hp[2]);
        float2 f3 = __half22float2(hp[3]);
        a[0] += wgt * f0.x; a[1] += wgt * f0.y;
        a[2] += wgt * f1.x; a[3] += wgt * f1.y;
        a[4] += wgt * f2.x; a[5] += wgt * f2.y;
        a[6] += wgt * f3.x; a[7] += wgt * f3.y;
    }

    float inv = 1.f / wsum;
    float* o = g_h1 + (size_t)n * HD1 + hh * HID + db;
    const float* bp = b1 + hh * HID + db;
#pragma unroll
    for (int k = 0; k < 8; k++) {
        float v = a[k] * inv + bp[k];
        a[k] = v > 0.f ? v : (__expf(v) - 1.f);   // ELU
    }
    *(float4*)o = make_float4(a[0], a[1], a[2], a[3]);
    *(float4*)(o + 4) = make_float4(a[4], a[5], a[6], a[7]);
}

// ---------------- layer 2 aggregation ----------------
__global__ void agg2_kernel(const float* __restrict__ b2, float* __restrict__ out) {
    int n = (blockIdx.x * blockDim.x + threadIdx.x) >> 5;
    if (n >= NNODES) return;
    int lane = threadIdx.x & 31;

    float ern = g_er2[n];
    float wsum = 0.f;
    float a0 = 0.f, a1 = 0.f;

    int beg = g_off[n], end = g_off[n + 1];
    for (int e = beg; e < end; e++) {
        int s = g_csr_src[e];
        float x = g_el2[s] + ern;
        x = fmaxf(x, 0.2f * x);
        float wgt = __expf(x);
        wsum += wgt;
        float2 f = *(const float2*)(g_feat2 + (size_t)s * OUT_DIM + lane * 2);
        a0 += wgt * f.x;
        a1 += wgt * f.y;
    }

    float inv = 1.f / wsum;
    out[(size_t)n * OUT_DIM + lane * 2 + 0] = a0 * inv + b2[lane * 2 + 0];
    out[(size_t)n * OUT_DIM + lane * 2 + 1] = a1 * inv + b2[lane * 2 + 1];
}

// ---------------- launch ----------------
extern "C" void kernel_launch(void* const* d_in, const int* in_sizes, int n_in,
                              void* d_out, int out_size) {
    const float* h   = (const float*)d_in[0];
    const float* W1  = (const float*)d_in[1];
    const float* al1 = (const float*)d_in[2];
    const float* ar1 = (const float*)d_in[3];
    const float* b1  = (const float*)d_in[4];
    const float* W2  = (const float*)d_in[5];
    const float* al2 = (const float*)d_in[6];
    const float* ar2 = (const float*)d_in[7];
    const float* b2  = (const float*)d_in[8];
    const int*   src = (const int*)d_in[9];
    const int*   dst = (const int*)d_in[10];
    float* out = (float*)d_out;

    float* h1p;   cudaGetSymbolAddress((void**)&h1p, g_h1);
    float* feat2; cudaGetSymbolAddress((void**)&feat2, g_feat2);

    static cudaStream_t s_csr = nullptr;
    static cudaEvent_t ev_fork = nullptr, ev_join = nullptr;
    if (s_csr == nullptr) {
        cudaStreamCreateWithFlags(&s_csr, cudaStreamNonBlocking);
        cudaEventCreateWithFlags(&ev_fork, cudaEventDisableTiming);
        cudaEventCreateWithFlags(&ev_join, cudaEventDisableTiming);
    }

    const int nwarpblocks = (NNODES * 32 + 255) / 256;
    const int eblocks = (NEDGES + 255) / 256;

    // fork: CSR build concurrent with GEMM1
    cudaEventRecord(ev_fork, 0);
    cudaStreamWaitEvent(s_csr, ev_fork, 0);
    zero_cnt_kernel<<<(NNODES + 255) / 256, 256, 0, s_csr>>>();
    hist_kernel<<<eblocks, 256, 0, s_csr>>>(dst);
    scan_kernel<<<1, 1024, 0, s_csr>>>();
    scatter_kernel<<<eblocks, 256, 0, s_csr>>>(src, dst);
    cudaEventRecord(ev_join, s_csr);

    // layer 1: packed-fp32 GEMM + fused el1/er1, fp16 feat output
    {
        dim3 grid(HD1 / BNT, (NNODES + BMT - 1) / BMT);
        pgemm_kernel<1><<<grid, 128>>>(h, NNODES, HD1, W1, nullptr, al1, ar1);
    }
    cudaStreamWaitEvent(0, ev_join, 0);
    agg1_kernel<<<nwarpblocks, 256>>>(b1);

    // layer 2: packed-fp32 GEMM + fused el2/er2
    {
        dim3 grid(OUT_DIM / BNT, (NNODES + BMT - 1) / BMT);
        pgemm_kernel<2><<<grid, 128>>>(h1p, NNODES, OUT_DIM, W2, feat2, al2, ar2);
    }
    agg2_kernel<<<nwarpblocks, 256>>>(b2, out);
}